// round 10
// baseline (speedup 1.0000x reference)
#include <cuda_runtime.h>
#include <cuda_fp16.h>
#include <cstdint>
#include <math.h>

// ---------------------------------------------------------------------------
// Problem constants
// ---------------------------------------------------------------------------
#define NTOK      49
#define DIM       384
#define NHEADS    12
#define HD        32
#define NWIN      4096
#define NMASK     1024
#define M_TOTAL   (NWIN * NTOK)     // 200704
#define QKV_N     (3 * DIM)         // 1152
#define KTOT      384
#define ATTN_SCALE 0.17677669529663687f
#define BM_STR    2404              // padded row (floats, 16B multiple)

// Scratch (__device__ globals; allocation-free rule)
__device__ __align__(128) __half g_qkvh[(size_t)M_TOTAL * QKV_N];
__device__ __align__(128) __half g_xh [(size_t)M_TOTAL * DIM];
__device__ __align__(128) __half g_ah [(size_t)M_TOTAL * DIM];
__device__ __align__(128) __half g_wqh[QKV_N * DIM];
__device__ __align__(128) __half g_wph[DIM * DIM];
__device__ __align__(128) float  g_bias12[NHEADS * BM_STR];
__device__ __align__(128) float  g_maskp[(size_t)NMASK * BM_STR];

// ---------------------------------------------------------------------------
// Helpers
// ---------------------------------------------------------------------------
__device__ __forceinline__ uint32_t smem_u32(const void* p) {
    uint32_t a;
    asm("{ .reg .u64 t; cvta.to.shared.u64 t, %1; cvt.u32.u64 %0, t; }" : "=r"(a) : "l"(p));
    return a;
}

__device__ __forceinline__ void cpa16(uint32_t dst, const void* src) {
    asm volatile("cp.async.cg.shared.global [%0], [%1], 16;" :: "r"(dst), "l"(src) : "memory");
}
#define CP_COMMIT() asm volatile("cp.async.commit_group;" ::: "memory")
#define CP_WAIT1()  asm volatile("cp.async.wait_group 1;" ::: "memory")
#define CP_WAIT0()  asm volatile("cp.async.wait_group 0;" ::: "memory")

__device__ __forceinline__ void mma_f16(float* d, const uint32_t* a, const uint32_t* b) {
    asm volatile(
        "mma.sync.aligned.m16n8k16.row.col.f32.f16.f16.f32 "
        "{%0,%1,%2,%3}, {%4,%5,%6,%7}, {%8,%9}, {%0,%1,%2,%3};"
        : "+f"(d[0]), "+f"(d[1]), "+f"(d[2]), "+f"(d[3])
        : "r"(a[0]), "r"(a[1]), "r"(a[2]), "r"(a[3]), "r"(b[0]), "r"(b[1]));
}

__device__ __forceinline__ void ldsm_x4(uint32_t* r, uint32_t addr) {
    asm volatile("ldmatrix.sync.aligned.m8n8.x4.shared.b16 {%0,%1,%2,%3}, [%4];"
                 : "=r"(r[0]), "=r"(r[1]), "=r"(r[2]), "=r"(r[3]) : "r"(addr));
}
__device__ __forceinline__ void ldsm_x4_t(uint32_t* r, uint32_t addr) {
    asm volatile("ldmatrix.sync.aligned.m8n8.x4.trans.shared.b16 {%0,%1,%2,%3}, [%4];"
                 : "=r"(r[0]), "=r"(r[1]), "=r"(r[2]), "=r"(r[3]) : "r"(addr));
}

// ---------------------------------------------------------------------------
// fp16 tensor-core GEMM; fragment-hoisted inner loop.
// ---------------------------------------------------------------------------
#define BKH      32
#define NSTAGE   3
#define KITERS   (KTOT / BKH)
#define SROWW    20
#define STAGEW   (128 * SROWW)
#define SMEM_TOT (NSTAGE * STAGEW * 2 * 4)

template <typename OutT>
__global__ __launch_bounds__(256, 2)
void gemm_mma_kernel(const __half* __restrict__ A,
                     const __half* __restrict__ W,
                     const float* __restrict__ bias,
                     OutT* __restrict__ C,
                     int Ntot) {
    extern __shared__ __align__(16) uint32_t sm[];
    uint32_t* Asm = sm;
    uint32_t* Bsm = sm + NSTAGE * STAGEW;

    const int tid  = threadIdx.x;
    const int warp = tid >> 5;
    const int lane = tid & 31;
    const int gid  = lane >> 2;
    const int tig  = lane & 3;
    const int wm   = warp & 1;
    const int wn   = warp >> 1;
    const int mb   = blockIdx.y * 128;
    const int nb   = blockIdx.x * 128;

    const int aLane = ((lane & 7) + 8 * ((lane >> 3) & 1)) * SROWW + 4 * (lane >> 4);
    const int bLane = ((lane & 7) + 8 * (lane >> 4)) * SROWW + 4 * ((lane >> 3) & 1);

    auto load_stage = [&](int s, int kt) {
        uint32_t* as = Asm + s * STAGEW;
        uint32_t* bs = Bsm + s * STAGEW;
        const int k0 = kt * BKH;
        #pragma unroll
        for (int i = 0; i < 2; i++) {
            const int f = tid + i * 256;
            const int m = f >> 2;
            const int g = f & 3;
            cpa16(smem_u32(as + m * SROWW + g * 4), A + (size_t)(mb + m) * KTOT + k0 + g * 8);
            cpa16(smem_u32(bs + m * SROWW + g * 4), W + (size_t)(nb + m) * KTOT + k0 + g * 8);
        }
    };

    float acc[4][4][4];
    #pragma unroll
    for (int mt = 0; mt < 4; mt++)
        #pragma unroll
        for (int nt = 0; nt < 4; nt++)
            #pragma unroll
            for (int r = 0; r < 4; r++) acc[mt][nt][r] = 0.0f;

    load_stage(0, 0); CP_COMMIT();
    load_stage(1, 1); CP_COMMIT();

    for (int kt = 0; kt < KITERS; ++kt) {
        CP_WAIT1();
        __syncthreads();

        const int s = kt % NSTAGE;
        if (kt + 2 < KITERS) load_stage((kt + 2) % NSTAGE, kt + 2);
        CP_COMMIT();

        const uint32_t aS = smem_u32(Asm + s * STAGEW);
        const uint32_t bS = smem_u32(Bsm + s * STAGEW);

        // hoist ALL fragment loads for both k16 steps, then stream MMAs
        uint32_t af[2][4][4], bf[2][4][2];
        #pragma unroll
        for (int ks = 0; ks < 2; ks++) {
            const int kw = ks * 8;
            #pragma unroll
            for (int mt = 0; mt < 4; mt++) {
                const int base = (wm * 64 + mt * 16) * SROWW + kw + aLane;
                ldsm_x4(af[ks][mt], aS + base * 4);
            }
            #pragma unroll
            for (int np = 0; np < 2; np++) {
                uint32_t q[4];
                const int base = (wn * 32 + np * 16) * SROWW + kw + bLane;
                ldsm_x4(q, bS + base * 4);
                bf[ks][2 * np + 0][0] = q[0]; bf[ks][2 * np + 0][1] = q[1];
                bf[ks][2 * np + 1][0] = q[2]; bf[ks][2 * np + 1][1] = q[3];
            }
        }
        #pragma unroll
        for (int ks = 0; ks < 2; ks++)
            #pragma unroll
            for (int mt = 0; mt < 4; mt++)
                #pragma unroll
                for (int nt = 0; nt < 4; nt++)
                    mma_f16(acc[mt][nt], af[ks][mt], bf[ks][nt]);
    }

    #pragma unroll
    for (int mt = 0; mt < 4; mt++) {
        const int row = mb + wm * 64 + mt * 16 + gid;
        #pragma unroll
        for (int nt = 0; nt < 4; nt++) {
            const int col = nb + wn * 32 + nt * 8 + 2 * tig;
            const float b0 = bias[col], b1 = bias[col + 1];
            if constexpr (sizeof(OutT) == 4) {
                float2 v0 = make_float2(acc[mt][nt][0] + b0, acc[mt][nt][1] + b1);
                float2 v1 = make_float2(acc[mt][nt][2] + b0, acc[mt][nt][3] + b1);
                *reinterpret_cast<float2*>((float*)C + (size_t)row * Ntot + col)       = v0;
                *reinterpret_cast<float2*>((float*)C + (size_t)(row + 8) * Ntot + col) = v1;
            } else {
                __half2 h0 = __floats2half2_rn(acc[mt][nt][0] + b0, acc[mt][nt][1] + b1);
                __half2 h1 = __floats2half2_rn(acc[mt][nt][2] + b0, acc[mt][nt][3] + b1);
                *reinterpret_cast<__half2*>((__half*)C + (size_t)row * Ntot + col)       = h0;
                *reinterpret_cast<__half2*>((__half*)C + (size_t)(row + 8) * Ntot + col) = h1;
            }
        }
    }
}

// ---------------------------------------------------------------------------
// Prep kernels (flat grids)
// ---------------------------------------------------------------------------
__global__ void f2h_kernel(const float4* __restrict__ in,
                           uint2* __restrict__ out, int n4) {
    int i = blockIdx.x * blockDim.x + threadIdx.x;
    if (i < n4) {
        float4 v = in[i];
        __half2 h0 = __floats2half2_rn(v.x, v.y);
        __half2 h1 = __floats2half2_rn(v.z, v.w);
        uint2 u;
        u.x = *reinterpret_cast<uint32_t*>(&h0);
        u.y = *reinterpret_cast<uint32_t*>(&h1);
        out[i] = u;
    }
}

__global__ void bias_prep_kernel(const float* __restrict__ rpb,
                                 const int* __restrict__ rel_idx,
                                 float* __restrict__ out) {
    int i = blockIdx.x * blockDim.x + threadIdx.x;
    if (i < NHEADS * BM_STR) {
        const int h = i / BM_STR;
        const int e = i - h * BM_STR;
        out[i] = (e < NTOK * NTOK) ? rpb[rel_idx[e] * NHEADS + h] : 0.0f;
    }
}

__global__ void mask_pad_kernel(const float* __restrict__ mask,
                                float* __restrict__ out, int n) {
    int i = blockIdx.x * blockDim.x + threadIdx.x;
    if (i < n) {
        const int m = i / BM_STR;
        const int e = i - m * BM_STR;
        out[i] = (e < NTOK * NTOK) ? mask[(size_t)m * (NTOK * NTOK) + e] : 0.0f;
    }
}

// ---------------------------------------------------------------------------
// Window attention (round-8 structure, dynamic smem, split bias/mask tables)
// One CTA (128 thr) per (window, head).
// ---------------------------------------------------------------------------
#define AOFF_QK  0         // Q 5120 + K 5120 (P[64][72] aliases this region)
#define AOFF_V   10240     // 5120
#define AOFF_SF  15360     // 49*57*4 = 11172 -> 11184
#define AOFF_BS  26544     // 9616
#define AOFF_MS  36160     // 9616
#define ATT_SMEM 45776

__global__ __launch_bounds__(128, 4)
void win_attn_kernel(const __half* __restrict__ qkv,
                     const float* __restrict__ bias12,
                     const float* __restrict__ maskp,
                     __half* __restrict__ attout) {
    extern __shared__ __align__(16) char smem[];
    const int w = blockIdx.x / NHEADS;
    const int h = blockIdx.x % NHEADS;
    const int tid  = threadIdx.x;
    const int warp = tid >> 5;
    const int lane = tid & 31;
    const int gid  = lane >> 2;
    const int tig  = lane & 3;

    __half (*Qh)[40] = reinterpret_cast<__half(*)[40]>(smem + AOFF_QK);
    __half (*Kh)[40] = reinterpret_cast<__half(*)[40]>(smem + AOFF_QK + 5120);
    __half (*Vh)[40] = reinterpret_cast<__half(*)[40]>(smem + AOFF_V);
    __half (*Ph)[72] = reinterpret_cast<__half(*)[72]>(smem + AOFF_QK);
    float  (*Sf)[57] = reinterpret_cast<float(*)[57]>(smem + AOFF_SF);
    float* Bs = reinterpret_cast<float*>(smem + AOFF_BS);
    float* Ms = reinterpret_cast<float*>(smem + AOFF_MS);

    // ---- Prefetch: qkv rows + bias row + mask row ----
    const __half* base = qkv + (size_t)w * NTOK * QKV_N + h * HD;
    for (int idx = tid; idx < 3 * NTOK * 4; idx += 128) {
        const int m = idx / (NTOK * 4);
        const int rem = idx - m * (NTOK * 4);
        const int i = rem >> 2;
        const int g = rem & 3;
        __half* dst = (m == 0) ? &Qh[i][0] : (m == 1) ? &Kh[i][0] : &Vh[i][0];
        cpa16(smem_u32(dst + g * 8), base + (size_t)i * QKV_N + m * DIM + g * 8);
    }
    {
        const float* brow = bias12 + h * BM_STR;
        const float* mrow = maskp + (size_t)(w & (NMASK - 1)) * BM_STR;
        for (int idx = tid; idx < BM_STR / 4; idx += 128) {
            cpa16(smem_u32(Bs + idx * 4), brow + idx * 4);
            cpa16(smem_u32(Ms + idx * 4), mrow + idx * 4);
        }
    }
    CP_COMMIT();

    // ---- Zero pad rows 49..63 of Q/K/V while loads are in flight ----
    const uint4 z4 = make_uint4(0, 0, 0, 0);
    for (int idx = tid; idx < 225; idx += 128) {
        const int a = idx / 75;
        const int rem = idx - a * 75;
        const int r = 49 + rem / 5;
        const int g = rem % 5;
        __half* dst = (a == 0) ? &Qh[r][0] : (a == 1) ? &Kh[r][0] : &Vh[r][0];
        reinterpret_cast<uint4*>(dst)[g] = z4;
    }
    CP_WAIT0();
    __syncthreads();

    // ---- Scores: S = Q K^T ----
    const uint32_t QS = smem_u32(&Qh[0][0]);
    const uint32_t KS = smem_u32(&Kh[0][0]);
    const int aL = ((lane & 7) + 8 * ((lane >> 3) & 1)) * 20 + 4 * (lane >> 4);
    const int bL = ((lane & 7) + 8 * (lane >> 4)) * 20 + 4 * ((lane >> 3) & 1);

    float acc[8][4];
    #pragma unroll
    for (int a = 0; a < 8; a++)
        #pragma unroll
        for (int r = 0; r < 4; r++) acc[a][r] = 0.0f;

    #pragma unroll
    for (int ks = 0; ks < 2; ks++) {
        uint32_t af[4];
        ldsm_x4(af, QS + (uint32_t)(warp * 16 * 20 + ks * 8 + aL) * 4);
        #pragma unroll
        for (int nb = 0; nb < 4; nb++) {
            uint32_t q[4];
            ldsm_x4(q, KS + (uint32_t)(nb * 16 * 20 + ks * 8 + bL) * 4);
            mma_f16(acc[nb * 2 + 0], af, q + 0);
            mma_f16(acc[nb * 2 + 1], af, q + 2);
        }
    }

    // scores + scale + bias + mask (smem tables)
    {
        const int i0 = warp * 16 + gid;
        #pragma unroll
        for (int nt = 0; nt < 8; nt++) {
            const int j = nt * 8 + 2 * tig;
            if (j < NTOK) {
                #pragma unroll
                for (int rr = 0; rr < 2; rr++) {
                    const int i = i0 + rr * 8;
                    if (i < NTOK) {
                        const int e = i * NTOK + j;
                        Sf[i][j] = fmaf(acc[nt][rr * 2], ATTN_SCALE, Bs[e] + Ms[e]);
                        if (j + 1 < NTOK)
                            Sf[i][j + 1] = fmaf(acc[nt][rr * 2 + 1], ATTN_SCALE,
                                                Bs[e + 1] + Ms[e + 1]);
                    }
                }
            }
        }
    }
    __syncthreads();   // Sf complete; Q/K dead -> Ph region reusable

    // ---- Softmax rows (threads 0..48) || P pad-zeroing (threads 49..127) ----
    if (tid < NTOK) {
        const int i = tid;
        float m = -1e30f;
        #pragma unroll 7
        for (int j = 0; j < NTOK; j++) m = fmaxf(m, Sf[i][j]);
        float s = 0.0f;
        #pragma unroll 7
        for (int j = 0; j < NTOK; j++) {
            const float e = __expf(Sf[i][j] - m);
            Sf[i][j] = e;
            s += e;
        }
        const float inv = 1.0f / s;
        #pragma unroll 7
        for (int j = 0; j < NTOK; j++)
            Ph[i][j] = __float2half_rn(Sf[i][j] * inv);
        #pragma unroll
        for (int j = NTOK; j < 56; j++)
            Ph[i][j] = __ushort_as_half((unsigned short)0);
    } else {
        for (int idx = tid - NTOK; idx < 233; idx += 128 - NTOK) {
            int r, c;
            if (idx < 135) { r = 49 + idx / 9; c = (idx % 9) * 8; }
            else           { const int q = idx - 135; r = q >> 1; c = 56 + (q & 1) * 8; }
            *reinterpret_cast<uint4*>(&Ph[r][c]) = z4;
        }
    }
    __syncthreads();

    // ---- PV: O = P V ----
    const uint32_t PS = smem_u32(&Ph[0][0]);
    const uint32_t VS = smem_u32(&Vh[0][0]);
    const int aLp = ((lane & 7) + 8 * ((lane >> 3) & 1)) * 36 + 4 * (lane >> 4);
    const int vL  = ((lane & 7) + 8 * ((lane >> 3) & 1)) * 20 + 4 * (lane >> 4);

    float pacc[4][4];
    #pragma unroll
    for (int a = 0; a < 4; a++)
        #pragma unroll
        for (int r = 0; r < 4; r++) pacc[a][r] = 0.0f;

    #pragma unroll
    for (int ks = 0; ks < 4; ks++) {
        uint32_t pf[4];
        ldsm_x4(pf, PS + (uint32_t)(warp * 16 * 36 + ks * 8 + aLp) * 4);
        uint32_t v0[4], v1[4];
        ldsm_x4_t(v0, VS + (uint32_t)(ks * 16 * 20 + vL) * 4);
        ldsm_x4_t(v1, VS + (uint32_t)(ks * 16 * 20 + 8 + vL) * 4);
        mma_f16(pacc[0], pf, v0 + 0);
        mma_f16(pacc[1], pf, v0 + 2);
        mma_f16(pacc[2], pf, v1 + 0);
        mma_f16(pacc[3], pf, v1 + 2);
    }

    // ---- Store O (fp16) ----
    {
        __half* ob = attout + (size_t)w * NTOK * DIM + h * HD;
        const int i0 = warp * 16 + gid;
        #pragma unroll
        for (int nt = 0; nt < 4; nt++) {
            const int d = nt * 8 + 2 * tig;
            #pragma unroll
            for (int rr = 0; rr < 2; rr++) {
                const int i = i0 + rr * 8;
                if (i < NTOK) {
                    __half2 hv = __floats2half2_rn(pacc[nt][rr * 2], pacc[nt][rr * 2 + 1]);
                    *reinterpret_cast<__half2*>(ob + (size_t)i * DIM + d) = hv;
                }
            }
        }
    }
}

// ---------------------------------------------------------------------------
// Launch
// ---------------------------------------------------------------------------
extern "C" void kernel_launch(void* const* d_in, const int* in_sizes, int n_in,
                              void* d_out, int out_size) {
    const float* x      = (const float*)d_in[0];
    const float* mask   = (const float*)d_in[1];
    const float* rpb    = (const float*)d_in[2];
    const float* qkv_w  = (const float*)d_in[3];
    const float* qkv_b  = (const float*)d_in[4];
    const float* proj_w = (const float*)d_in[5];
    const float* proj_b = (const float*)d_in[6];
    const int*   rel_i  = (const int*)d_in[7];
    float* out = (float*)d_out;

    __half *qkvh, *xh, *ah, *wqh, *wph;
    float *biasb, *maskb;
    cudaGetSymbolAddress((void**)&qkvh, g_qkvh);
    cudaGetSymbolAddress((void**)&xh,  g_xh);
    cudaGetSymbolAddress((void**)&ah,  g_ah);
    cudaGetSymbolAddress((void**)&wqh, g_wqh);
    cudaGetSymbolAddress((void**)&wph, g_wph);
    cudaGetSymbolAddress((void**)&biasb, g_bias12);
    cudaGetSymbolAddress((void**)&maskb, g_maskp);

    cudaFuncSetAttribute(gemm_mma_kernel<__half>,
                         cudaFuncAttributeMaxDynamicSharedMemorySize, SMEM_TOT);
    cudaFuncSetAttribute(gemm_mma_kernel<float>,
                         cudaFuncAttributeMaxDynamicSharedMemorySize, SMEM_TOT);
    cudaFuncSetAttribute(win_attn_kernel,
                         cudaFuncAttributeMaxDynamicSharedMemorySize, ATT_SMEM);

    // prep: conversions + padded bias/mask tables
    {
        int n4 = (M_TOTAL * DIM) / 4;
        f2h_kernel<<<(n4 + 255) / 256, 256>>>((const float4*)x, (uint2*)xh, n4);
        int w4 = (QKV_N * DIM) / 4;
        f2h_kernel<<<(w4 + 255) / 256, 256>>>((const float4*)qkv_w, (uint2*)wqh, w4);
        int p4 = (DIM * DIM) / 4;
        f2h_kernel<<<(p4 + 255) / 256, 256>>>((const float4*)proj_w, (uint2*)wph, p4);
        bias_prep_kernel<<<(NHEADS * BM_STR + 255) / 256, 256>>>(rpb, rel_i, biasb);
        int mn = NMASK * BM_STR;
        mask_pad_kernel<<<(mn + 255) / 256, 256>>>(mask, maskb, mn);
    }

    // 1) QKV projection -> fp16 qkv
    {
        dim3 grid(QKV_N / 128, M_TOTAL / 128);
        gemm_mma_kernel<__half><<<grid, 256, SMEM_TOT>>>(xh, wqh, qkv_b, qkvh, QKV_N);
    }

    // 2) Windowed attention (round-8 structure, split tables)
    win_attn_kernel<<<NWIN * NHEADS, 128, ATT_SMEM>>>(qkvh, biasb, maskb, ah);

    // 3) Output projection -> fp32 d_out
    {
        dim3 grid(DIM / 128, M_TOTAL / 128);
        gemm_mma_kernel<float><<<grid, 256, SMEM_TOT>>>(ah, wph, proj_b, out, DIM);
    }
}

// round 11
// speedup vs baseline: 1.0910x; 1.0910x over previous
#include <cuda_runtime.h>
#include <cuda_fp16.h>
#include <cstdint>
#include <math.h>

// ---------------------------------------------------------------------------
// Problem constants
// ---------------------------------------------------------------------------
#define NTOK      49
#define DIM       384
#define NHEADS    12
#define HD        32
#define NWIN      4096
#define NMASK     1024
#define M_TOTAL   (NWIN * NTOK)     // 200704
#define QKV_N     (3 * DIM)         // 1152
#define KTOT      384
#define ATTN_SCALE 0.17677669529663687f
#define BM_STR    2404              // padded bias+mask row (floats, 16B-aligned)

// Scratch (__device__ globals; allocation-free rule)
__device__ __align__(128) __half g_qkvh[(size_t)M_TOTAL * QKV_N];
__device__ __align__(128) __half g_xh [(size_t)M_TOTAL * DIM];
__device__ __align__(128) __half g_ah [(size_t)M_TOTAL * DIM];
__device__ __align__(128) __half g_wqh[QKV_N * DIM];
__device__ __align__(128) __half g_wph[DIM * DIM];
__device__ __align__(128) float  g_bm[(size_t)NMASK * NHEADS * BM_STR];  // bias+mask fused

// ---------------------------------------------------------------------------
// Helpers
// ---------------------------------------------------------------------------
__device__ __forceinline__ uint32_t smem_u32(const void* p) {
    uint32_t a;
    asm("{ .reg .u64 t; cvta.to.shared.u64 t, %1; cvt.u32.u64 %0, t; }" : "=r"(a) : "l"(p));
    return a;
}

__device__ __forceinline__ void cpa16(uint32_t dst, const void* src) {
    asm volatile("cp.async.cg.shared.global [%0], [%1], 16;" :: "r"(dst), "l"(src) : "memory");
}
#define CP_COMMIT() asm volatile("cp.async.commit_group;" ::: "memory")
#define CP_WAIT1()  asm volatile("cp.async.wait_group 1;" ::: "memory")
#define CP_WAIT0()  asm volatile("cp.async.wait_group 0;" ::: "memory")

__device__ __forceinline__ void mma_f16(float* d, const uint32_t* a, const uint32_t* b) {
    asm volatile(
        "mma.sync.aligned.m16n8k16.row.col.f32.f16.f16.f32 "
        "{%0,%1,%2,%3}, {%4,%5,%6,%7}, {%8,%9}, {%0,%1,%2,%3};"
        : "+f"(d[0]), "+f"(d[1]), "+f"(d[2]), "+f"(d[3])
        : "r"(a[0]), "r"(a[1]), "r"(a[2]), "r"(a[3]), "r"(b[0]), "r"(b[1]));
}

__device__ __forceinline__ void ldsm_x4(uint32_t* r, uint32_t addr) {
    asm volatile("ldmatrix.sync.aligned.m8n8.x4.shared.b16 {%0,%1,%2,%3}, [%4];"
                 : "=r"(r[0]), "=r"(r[1]), "=r"(r[2]), "=r"(r[3]) : "r"(addr));
}
__device__ __forceinline__ void ldsm_x4_t(uint32_t* r, uint32_t addr) {
    asm volatile("ldmatrix.sync.aligned.m8n8.x4.trans.shared.b16 {%0,%1,%2,%3}, [%4];"
                 : "=r"(r[0]), "=r"(r[1]), "=r"(r[2]), "=r"(r[3]) : "r"(addr));
}

// ---------------------------------------------------------------------------
// fp16 tensor-core GEMM (exact round-6/8 proven version, NO fragment hoist)
// ---------------------------------------------------------------------------
#define BKH      32
#define NSTAGE   3
#define KITERS   (KTOT / BKH)
#define SROWW    20
#define STAGEW   (128 * SROWW)
#define SMEM_TOT (NSTAGE * STAGEW * 2 * 4)

template <typename OutT>
__global__ __launch_bounds__(256, 2)
void gemm_mma_kernel(const __half* __restrict__ A,
                     const __half* __restrict__ W,
                     const float* __restrict__ bias,
                     OutT* __restrict__ C,
                     int Ntot) {
    extern __shared__ __align__(16) uint32_t sm[];
    uint32_t* Asm = sm;
    uint32_t* Bsm = sm + NSTAGE * STAGEW;

    const int tid  = threadIdx.x;
    const int warp = tid >> 5;
    const int lane = tid & 31;
    const int gid  = lane >> 2;
    const int tig  = lane & 3;
    const int wm   = warp & 1;
    const int wn   = warp >> 1;
    const int mb   = blockIdx.y * 128;
    const int nb   = blockIdx.x * 128;

    const int aLane = ((lane & 7) + 8 * ((lane >> 3) & 1)) * SROWW + 4 * (lane >> 4);
    const int bLane = ((lane & 7) + 8 * (lane >> 4)) * SROWW + 4 * ((lane >> 3) & 1);

    auto load_stage = [&](int s, int kt) {
        uint32_t* as = Asm + s * STAGEW;
        uint32_t* bs = Bsm + s * STAGEW;
        const int k0 = kt * BKH;
        #pragma unroll
        for (int i = 0; i < 2; i++) {
            const int f = tid + i * 256;
            const int m = f >> 2;
            const int g = f & 3;
            cpa16(smem_u32(as + m * SROWW + g * 4), A + (size_t)(mb + m) * KTOT + k0 + g * 8);
            cpa16(smem_u32(bs + m * SROWW + g * 4), W + (size_t)(nb + m) * KTOT + k0 + g * 8);
        }
    };

    float acc[4][4][4];
    #pragma unroll
    for (int mt = 0; mt < 4; mt++)
        #pragma unroll
        for (int nt = 0; nt < 4; nt++)
            #pragma unroll
            for (int r = 0; r < 4; r++) acc[mt][nt][r] = 0.0f;

    load_stage(0, 0); CP_COMMIT();
    load_stage(1, 1); CP_COMMIT();

    for (int kt = 0; kt < KITERS; ++kt) {
        CP_WAIT1();
        __syncthreads();

        const int s = kt % NSTAGE;
        if (kt + 2 < KITERS) load_stage((kt + 2) % NSTAGE, kt + 2);
        CP_COMMIT();

        const uint32_t aS = smem_u32(Asm + s * STAGEW);
        const uint32_t bS = smem_u32(Bsm + s * STAGEW);

        #pragma unroll
        for (int ks = 0; ks < 2; ks++) {
            const int kw = ks * 8;
            uint32_t af[4][4], bf[4][2];
            #pragma unroll
            for (int mt = 0; mt < 4; mt++) {
                const int base = (wm * 64 + mt * 16) * SROWW + kw + aLane;
                ldsm_x4(af[mt], aS + base * 4);
            }
            #pragma unroll
            for (int np = 0; np < 2; np++) {
                uint32_t q[4];
                const int base = (wn * 32 + np * 16) * SROWW + kw + bLane;
                ldsm_x4(q, bS + base * 4);
                bf[2 * np + 0][0] = q[0]; bf[2 * np + 0][1] = q[1];
                bf[2 * np + 1][0] = q[2]; bf[2 * np + 1][1] = q[3];
            }
            #pragma unroll
            for (int mt = 0; mt < 4; mt++)
                #pragma unroll
                for (int nt = 0; nt < 4; nt++)
                    mma_f16(acc[mt][nt], af[mt], bf[nt]);
        }
    }

    #pragma unroll
    for (int mt = 0; mt < 4; mt++) {
        const int row = mb + wm * 64 + mt * 16 + gid;
        #pragma unroll
        for (int nt = 0; nt < 4; nt++) {
            const int col = nb + wn * 32 + nt * 8 + 2 * tig;
            const float b0 = bias[col], b1 = bias[col + 1];
            if constexpr (sizeof(OutT) == 4) {
                float2 v0 = make_float2(acc[mt][nt][0] + b0, acc[mt][nt][1] + b1);
                float2 v1 = make_float2(acc[mt][nt][2] + b0, acc[mt][nt][3] + b1);
                *reinterpret_cast<float2*>((float*)C + (size_t)row * Ntot + col)       = v0;
                *reinterpret_cast<float2*>((float*)C + (size_t)(row + 8) * Ntot + col) = v1;
            } else {
                __half2 h0 = __floats2half2_rn(acc[mt][nt][0] + b0, acc[mt][nt][1] + b1);
                __half2 h1 = __floats2half2_rn(acc[mt][nt][2] + b0, acc[mt][nt][3] + b1);
                *reinterpret_cast<__half2*>((__half*)C + (size_t)row * Ntot + col)       = h0;
                *reinterpret_cast<__half2*>((__half*)C + (size_t)(row + 8) * Ntot + col) = h1;
            }
        }
    }
}

// ---------------------------------------------------------------------------
// fp32 -> fp16 conversion; fused bias+mask precompute (vectorized writes)
// ---------------------------------------------------------------------------
__global__ void f2h_kernel(const float4* __restrict__ in,
                           uint2* __restrict__ out, int n4) {
    int i = blockIdx.x * blockDim.x + threadIdx.x;
    if (i < n4) {
        float4 v = in[i];
        __half2 h0 = __floats2half2_rn(v.x, v.y);
        __half2 h1 = __floats2half2_rn(v.z, v.w);
        uint2 u;
        u.x = *reinterpret_cast<uint32_t*>(&h0);
        u.y = *reinterpret_cast<uint32_t*>(&h1);
        out[i] = u;
    }
}

// out[(m*12+h)*BM_STR + e] = rpb[rel_idx[e]*12 + h] + mask[m*2401 + e]
__global__ void bm_prep_kernel(const float* __restrict__ rpb,
                               const int* __restrict__ rel_idx,
                               const float* __restrict__ mask,
                               float* __restrict__ out) {
    const int row = blockIdx.x;              // 0 .. NMASK*NHEADS-1 (m-major)
    const int m = row / NHEADS;
    const int h = row - m * NHEADS;
    const float* mrow = mask + (size_t)m * (NTOK * NTOK);
    float4* orow = reinterpret_cast<float4*>(out + (size_t)row * BM_STR);
    for (int g = threadIdx.x; g < BM_STR / 4; g += 256) {
        const int e0 = g * 4;
        float4 v;
        v.x = (e0 + 0 < NTOK * NTOK) ? rpb[rel_idx[e0 + 0] * NHEADS + h] + mrow[e0 + 0] : 0.0f;
        v.y = (e0 + 1 < NTOK * NTOK) ? rpb[rel_idx[e0 + 1] * NHEADS + h] + mrow[e0 + 1] : 0.0f;
        v.z = (e0 + 2 < NTOK * NTOK) ? rpb[rel_idx[e0 + 2] * NHEADS + h] + mrow[e0 + 2] : 0.0f;
        v.w = (e0 + 3 < NTOK * NTOK) ? rpb[rel_idx[e0 + 3] * NHEADS + h] + mrow[e0 + 3] : 0.0f;
        orow[g] = v;
    }
}

// ---------------------------------------------------------------------------
// Window attention (round-8 structure + warp-parallel softmax).
// One CTA (128 thr) per (window, head); 6 CTAs/SM.
// ---------------------------------------------------------------------------
__global__ __launch_bounds__(128, 6)
void win_attn_kernel(const __half* __restrict__ qkv,
                     const float* __restrict__ bm,
                     __half* __restrict__ attout) {
    const int w = blockIdx.x / NHEADS;
    const int h = blockIdx.x % NHEADS;
    const int tid  = threadIdx.x;
    const int warp = tid >> 5;
    const int lane = tid & 31;
    const int gid  = lane >> 2;
    const int tig  = lane & 3;

    // Q/K region (10240 B) reused for P (9216 B) after the score MMA.
    __shared__ __align__(16) char  ub[64 * 40 * 2 * 2];
    __shared__ __align__(16) __half Vh[64][40];
    __shared__ __align__(16) float  Sf[NTOK][57];
    __shared__ __align__(16) float  BMs[BM_STR];

    __half (*Qh)[40] = reinterpret_cast<__half(*)[40]>(ub);
    __half (*Kh)[40] = reinterpret_cast<__half(*)[40]>(ub + 64 * 40 * 2);
    __half (*Ph)[72] = reinterpret_cast<__half(*)[72]>(ub);

    // ---- Prefetch: qkv rows (588 x 16B) + bm row (601 x 16B) ----
    const __half* base = qkv + (size_t)w * NTOK * QKV_N + h * HD;
    for (int idx = tid; idx < 3 * NTOK * 4; idx += 128) {
        const int m = idx / (NTOK * 4);
        const int rem = idx - m * (NTOK * 4);
        const int i = rem >> 2;
        const int g = rem & 3;
        __half* dst = (m == 0) ? &Qh[i][0] : (m == 1) ? &Kh[i][0] : &Vh[i][0];
        cpa16(smem_u32(dst + g * 8), base + (size_t)i * QKV_N + m * DIM + g * 8);
    }
    {
        const float* bmrow = bm + (size_t)((w & (NMASK - 1)) * NHEADS + h) * BM_STR;
        for (int idx = tid; idx < BM_STR / 4; idx += 128)
            cpa16(smem_u32(&BMs[idx * 4]), bmrow + idx * 4);
    }
    CP_COMMIT();

    // ---- Zero pad rows 49..63 of Q/K/V while loads are in flight ----
    const uint4 z4 = make_uint4(0, 0, 0, 0);
    for (int idx = tid; idx < 225; idx += 128) {
        const int a = idx / 75;
        const int rem = idx - a * 75;
        const int r = 49 + rem / 5;
        const int g = rem % 5;
        __half* dst = (a == 0) ? &Qh[r][0] : (a == 1) ? &Kh[r][0] : &Vh[r][0];
        reinterpret_cast<uint4*>(dst)[g] = z4;
    }
    CP_WAIT0();
    __syncthreads();

    // ---- Scores: S = Q K^T ----
    const uint32_t QS = smem_u32(&Qh[0][0]);
    const uint32_t KS = smem_u32(&Kh[0][0]);
    const int aL = ((lane & 7) + 8 * ((lane >> 3) & 1)) * 20 + 4 * (lane >> 4);
    const int bL = ((lane & 7) + 8 * (lane >> 4)) * 20 + 4 * ((lane >> 3) & 1);

    float acc[8][4];
    #pragma unroll
    for (int a = 0; a < 8; a++)
        #pragma unroll
        for (int r = 0; r < 4; r++) acc[a][r] = 0.0f;

    #pragma unroll
    for (int ks = 0; ks < 2; ks++) {
        uint32_t af[4];
        ldsm_x4(af, QS + (uint32_t)(warp * 16 * 20 + ks * 8 + aL) * 4);
        #pragma unroll
        for (int nb = 0; nb < 4; nb++) {
            uint32_t q[4];
            ldsm_x4(q, KS + (uint32_t)(nb * 16 * 20 + ks * 8 + bL) * 4);
            mma_f16(acc[nb * 2 + 0], af, q + 0);
            mma_f16(acc[nb * 2 + 1], af, q + 2);
        }
    }

    // scores + scale + fused bias/mask from smem
    {
        const int i0 = warp * 16 + gid;
        #pragma unroll
        for (int nt = 0; nt < 8; nt++) {
            const int j = nt * 8 + 2 * tig;
            if (j < NTOK) {
                #pragma unroll
                for (int rr = 0; rr < 2; rr++) {
                    const int i = i0 + rr * 8;
                    if (i < NTOK) {
                        const int e = i * NTOK + j;
                        Sf[i][j] = fmaf(acc[nt][rr * 2], ATTN_SCALE, BMs[e]);
                        if (j + 1 < NTOK)
                            Sf[i][j + 1] = fmaf(acc[nt][rr * 2 + 1], ATTN_SCALE, BMs[e + 1]);
                    }
                }
            }
        }
    }
    __syncthreads();   // Sf complete; Q/K dead -> Ph region reusable

    // ---- P pad zeroing (all threads) ----
    // rows 49..63 full width (15*9=135 uint4) + rows 0..48 cols 56..71 (49*2=98)
    for (int idx = tid; idx < 233; idx += 128) {
        int r, c;
        if (idx < 135) { r = 49 + idx / 9; c = (idx % 9) * 8; }
        else           { const int q = idx - 135; r = q >> 1; c = 56 + (q & 1) * 8; }
        *reinterpret_cast<uint4*>(&Ph[r][c]) = z4;
    }

    // ---- Warp-parallel softmax: 4 warps, rows strided by 4 ----
    for (int r = warp; r < NTOK; r += 4) {
        const float v0 = Sf[r][lane];
        const bool has2 = (lane + 32) < NTOK;
        const float v1 = has2 ? Sf[r][lane + 32] : -1e30f;
        float mx = fmaxf(v0, v1);
        #pragma unroll
        for (int off = 16; off; off >>= 1)
            mx = fmaxf(mx, __shfl_xor_sync(0xffffffffu, mx, off));
        const float e0 = __expf(v0 - mx);
        const float e1 = has2 ? __expf(v1 - mx) : 0.0f;
        float s = e0 + e1;
        #pragma unroll
        for (int off = 16; off; off >>= 1)
            s += __shfl_xor_sync(0xffffffffu, s, off);
        const float inv = 1.0f / s;
        Ph[r][lane] = __float2half_rn(e0 * inv);
        if (has2) Ph[r][lane + 32] = __float2half_rn(e1 * inv);
        if (lane < 7) Ph[r][49 + lane] = __ushort_as_half((unsigned short)0);
    }
    __syncthreads();

    // ---- PV: O = P V ----
    const uint32_t PS = smem_u32(&Ph[0][0]);
    const uint32_t VS = smem_u32(&Vh[0][0]);
    const int aLp = ((lane & 7) + 8 * ((lane >> 3) & 1)) * 36 + 4 * (lane >> 4);
    const int vL  = ((lane & 7) + 8 * ((lane >> 3) & 1)) * 20 + 4 * (lane >> 4);

    float pacc[4][4];
    #pragma unroll
    for (int a = 0; a < 4; a++)
        #pragma unroll
        for (int r = 0; r < 4; r++) pacc[a][r] = 0.0f;

    #pragma unroll
    for (int ks = 0; ks < 4; ks++) {
        uint32_t pf[4];
        ldsm_x4(pf, PS + (uint32_t)(warp * 16 * 36 + ks * 8 + aLp) * 4);
        uint32_t v0[4], v1[4];
        ldsm_x4_t(v0, VS + (uint32_t)(ks * 16 * 20 + vL) * 4);
        ldsm_x4_t(v1, VS + (uint32_t)(ks * 16 * 20 + 8 + vL) * 4);
        mma_f16(pacc[0], pf, v0 + 0);
        mma_f16(pacc[1], pf, v0 + 2);
        mma_f16(pacc[2], pf, v1 + 0);
        mma_f16(pacc[3], pf, v1 + 2);
    }

    // ---- Store O (fp16) ----
    {
        __half* ob = attout + (size_t)w * NTOK * DIM + h * HD;
        const int i0 = warp * 16 + gid;
        #pragma unroll
        for (int nt = 0; nt < 4; nt++) {
            const int d = nt * 8 + 2 * tig;
            #pragma unroll
            for (int rr = 0; rr < 2; rr++) {
                const int i = i0 + rr * 8;
                if (i < NTOK) {
                    __half2 hv = __floats2half2_rn(pacc[nt][rr * 2], pacc[nt][rr * 2 + 1]);
                    *reinterpret_cast<__half2*>(ob + (size_t)i * DIM + d) = hv;
                }
            }
        }
    }
}

// ---------------------------------------------------------------------------
// Launch
// ---------------------------------------------------------------------------
extern "C" void kernel_launch(void* const* d_in, const int* in_sizes, int n_in,
                              void* d_out, int out_size) {
    const float* x      = (const float*)d_in[0];
    const float* mask   = (const float*)d_in[1];
    const float* rpb    = (const float*)d_in[2];
    const float* qkv_w  = (const float*)d_in[3];
    const float* qkv_b  = (const float*)d_in[4];
    const float* proj_w = (const float*)d_in[5];
    const float* proj_b = (const float*)d_in[6];
    const int*   rel_i  = (const int*)d_in[7];
    float* out = (float*)d_out;

    __half *qkvh, *xh, *ah, *wqh, *wph;
    float* bmb;
    cudaGetSymbolAddress((void**)&qkvh, g_qkvh);
    cudaGetSymbolAddress((void**)&xh,  g_xh);
    cudaGetSymbolAddress((void**)&ah,  g_ah);
    cudaGetSymbolAddress((void**)&wqh, g_wqh);
    cudaGetSymbolAddress((void**)&wph, g_wph);
    cudaGetSymbolAddress((void**)&bmb, g_bm);

    cudaFuncSetAttribute(gemm_mma_kernel<__half>,
                         cudaFuncAttributeMaxDynamicSharedMemorySize, SMEM_TOT);
    cudaFuncSetAttribute(gemm_mma_kernel<float>,
                         cudaFuncAttributeMaxDynamicSharedMemorySize, SMEM_TOT);

    // conversions + fused bias/mask precompute
    {
        int n4 = (M_TOTAL * DIM) / 4;
        f2h_kernel<<<(n4 + 255) / 256, 256>>>((const float4*)x, (uint2*)xh, n4);
        int w4 = (QKV_N * DIM) / 4;
        f2h_kernel<<<(w4 + 255) / 256, 256>>>((const float4*)qkv_w, (uint2*)wqh, w4);
        int p4 = (DIM * DIM) / 4;
        f2h_kernel<<<(p4 + 255) / 256, 256>>>((const float4*)proj_w, (uint2*)wph, p4);
        bm_prep_kernel<<<NMASK * NHEADS, 256>>>(rpb, rel_i, mask, bmb);
    }

    // 1) QKV projection -> fp16 qkv
    {
        dim3 grid(QKV_N / 128, M_TOTAL / 128);
        gemm_mma_kernel<__half><<<grid, 256, SMEM_TOT>>>(xh, wqh, qkv_b, qkvh, QKV_N);
    }

    // 2) Windowed attention (tensor-core, prefetched operands)
    win_attn_kernel<<<NWIN * NHEADS, 128>>>(qkvh, bmb, ah);

    // 3) Output projection -> fp32 d_out
    {
        dim3 grid(DIM / 128, M_TOTAL / 128);
        gemm_mma_kernel<float><<<grid, 256, SMEM_TOT>>>(ah, wph, proj_b, out, DIM);
    }
}

// round 12
// speedup vs baseline: 1.1770x; 1.0789x over previous
#include <cuda_runtime.h>
#include <cuda_fp16.h>
#include <cstdint>
#include <math.h>

// ---------------------------------------------------------------------------
// Problem constants
// ---------------------------------------------------------------------------
#define NTOK      49
#define DIM       384
#define NHEADS    12
#define HD        32
#define NWIN      4096
#define NMASK     1024
#define M_TOTAL   (NWIN * NTOK)     // 200704
#define QKV_N     (3 * DIM)         // 1152
#define KTOT      384
#define ATTN_SCALE 0.17677669529663687f
#define BM_STR    2404              // padded bias+mask row (floats, 16B-aligned)

// Scratch (__device__ globals; allocation-free rule)
__device__ __align__(128) __half g_qkvh[(size_t)M_TOTAL * QKV_N];
__device__ __align__(128) __half g_xh [(size_t)M_TOTAL * DIM];
__device__ __align__(128) __half g_ah [(size_t)M_TOTAL * DIM];
__device__ __align__(128) __half g_wqh[QKV_N * DIM];
__device__ __align__(128) __half g_wph[DIM * DIM];
__device__ __align__(128) float  g_bias12[NHEADS * BM_STR];              // gathered rpb
__device__ __align__(128) float  g_bm[(size_t)NMASK * NHEADS * BM_STR];  // bias+mask fused

// ---------------------------------------------------------------------------
// Helpers
// ---------------------------------------------------------------------------
__device__ __forceinline__ uint32_t smem_u32(const void* p) {
    uint32_t a;
    asm("{ .reg .u64 t; cvta.to.shared.u64 t, %1; cvt.u32.u64 %0, t; }" : "=r"(a) : "l"(p));
    return a;
}

__device__ __forceinline__ void cpa16(uint32_t dst, const void* src) {
    asm volatile("cp.async.cg.shared.global [%0], [%1], 16;" :: "r"(dst), "l"(src) : "memory");
}
#define CP_COMMIT() asm volatile("cp.async.commit_group;" ::: "memory")
#define CP_WAIT1()  asm volatile("cp.async.wait_group 1;" ::: "memory")
#define CP_WAIT0()  asm volatile("cp.async.wait_group 0;" ::: "memory")

__device__ __forceinline__ void mma_f16(float* d, const uint32_t* a, const uint32_t* b) {
    asm volatile(
        "mma.sync.aligned.m16n8k16.row.col.f32.f16.f16.f32 "
        "{%0,%1,%2,%3}, {%4,%5,%6,%7}, {%8,%9}, {%0,%1,%2,%3};"
        : "+f"(d[0]), "+f"(d[1]), "+f"(d[2]), "+f"(d[3])
        : "r"(a[0]), "r"(a[1]), "r"(a[2]), "r"(a[3]), "r"(b[0]), "r"(b[1]));
}

__device__ __forceinline__ void ldsm_x4(uint32_t* r, uint32_t addr) {
    asm volatile("ldmatrix.sync.aligned.m8n8.x4.shared.b16 {%0,%1,%2,%3}, [%4];"
                 : "=r"(r[0]), "=r"(r[1]), "=r"(r[2]), "=r"(r[3]) : "r"(addr));
}
__device__ __forceinline__ void ldsm_x4_t(uint32_t* r, uint32_t addr) {
    asm volatile("ldmatrix.sync.aligned.m8n8.x4.trans.shared.b16 {%0,%1,%2,%3}, [%4];"
                 : "=r"(r[0]), "=r"(r[1]), "=r"(r[2]), "=r"(r[3]) : "r"(addr));
}

// ---------------------------------------------------------------------------
// fp16 tensor-core GEMM (exact round-8 proven version)
// ---------------------------------------------------------------------------
#define BKH      32
#define NSTAGE   3
#define KITERS   (KTOT / BKH)
#define SROWW    20
#define STAGEW   (128 * SROWW)
#define SMEM_TOT (NSTAGE * STAGEW * 2 * 4)

template <typename OutT>
__global__ __launch_bounds__(256, 2)
void gemm_mma_kernel(const __half* __restrict__ A,
                     const __half* __restrict__ W,
                     const float* __restrict__ bias,
                     OutT* __restrict__ C,
                     int Ntot) {
    extern __shared__ __align__(16) uint32_t sm[];
    uint32_t* Asm = sm;
    uint32_t* Bsm = sm + NSTAGE * STAGEW;

    const int tid  = threadIdx.x;
    const int warp = tid >> 5;
    const int lane = tid & 31;
    const int gid  = lane >> 2;
    const int tig  = lane & 3;
    const int wm   = warp & 1;
    const int wn   = warp >> 1;
    const int mb   = blockIdx.y * 128;
    const int nb   = blockIdx.x * 128;

    const int aLane = ((lane & 7) + 8 * ((lane >> 3) & 1)) * SROWW + 4 * (lane >> 4);
    const int bLane = ((lane & 7) + 8 * (lane >> 4)) * SROWW + 4 * ((lane >> 3) & 1);

    auto load_stage = [&](int s, int kt) {
        uint32_t* as = Asm + s * STAGEW;
        uint32_t* bs = Bsm + s * STAGEW;
        const int k0 = kt * BKH;
        #pragma unroll
        for (int i = 0; i < 2; i++) {
            const int f = tid + i * 256;
            const int m = f >> 2;
            const int g = f & 3;
            cpa16(smem_u32(as + m * SROWW + g * 4), A + (size_t)(mb + m) * KTOT + k0 + g * 8);
            cpa16(smem_u32(bs + m * SROWW + g * 4), W + (size_t)(nb + m) * KTOT + k0 + g * 8);
        }
    };

    float acc[4][4][4];
    #pragma unroll
    for (int mt = 0; mt < 4; mt++)
        #pragma unroll
        for (int nt = 0; nt < 4; nt++)
            #pragma unroll
            for (int r = 0; r < 4; r++) acc[mt][nt][r] = 0.0f;

    load_stage(0, 0); CP_COMMIT();
    load_stage(1, 1); CP_COMMIT();

    for (int kt = 0; kt < KITERS; ++kt) {
        CP_WAIT1();
        __syncthreads();

        const int s = kt % NSTAGE;
        if (kt + 2 < KITERS) load_stage((kt + 2) % NSTAGE, kt + 2);
        CP_COMMIT();

        const uint32_t aS = smem_u32(Asm + s * STAGEW);
        const uint32_t bS = smem_u32(Bsm + s * STAGEW);

        #pragma unroll
        for (int ks = 0; ks < 2; ks++) {
            const int kw = ks * 8;
            uint32_t af[4][4], bf[4][2];
            #pragma unroll
            for (int mt = 0; mt < 4; mt++) {
                const int base = (wm * 64 + mt * 16) * SROWW + kw + aLane;
                ldsm_x4(af[mt], aS + base * 4);
            }
            #pragma unroll
            for (int np = 0; np < 2; np++) {
                uint32_t q[4];
                const int base = (wn * 32 + np * 16) * SROWW + kw + bLane;
                ldsm_x4(q, bS + base * 4);
                bf[2 * np + 0][0] = q[0]; bf[2 * np + 0][1] = q[1];
                bf[2 * np + 1][0] = q[2]; bf[2 * np + 1][1] = q[3];
            }
            #pragma unroll
            for (int mt = 0; mt < 4; mt++)
                #pragma unroll
                for (int nt = 0; nt < 4; nt++)
                    mma_f16(acc[mt][nt], af[mt], bf[nt]);
        }
    }

    #pragma unroll
    for (int mt = 0; mt < 4; mt++) {
        const int row = mb + wm * 64 + mt * 16 + gid;
        #pragma unroll
        for (int nt = 0; nt < 4; nt++) {
            const int col = nb + wn * 32 + nt * 8 + 2 * tig;
            const float b0 = bias[col], b1 = bias[col + 1];
            if constexpr (sizeof(OutT) == 4) {
                float2 v0 = make_float2(acc[mt][nt][0] + b0, acc[mt][nt][1] + b1);
                float2 v1 = make_float2(acc[mt][nt][2] + b0, acc[mt][nt][3] + b1);
                *reinterpret_cast<float2*>((float*)C + (size_t)row * Ntot + col)       = v0;
                *reinterpret_cast<float2*>((float*)C + (size_t)(row + 8) * Ntot + col) = v1;
            } else {
                __half2 h0 = __floats2half2_rn(acc[mt][nt][0] + b0, acc[mt][nt][1] + b1);
                __half2 h1 = __floats2half2_rn(acc[mt][nt][2] + b0, acc[mt][nt][3] + b1);
                *reinterpret_cast<__half2*>((__half*)C + (size_t)row * Ntot + col)       = h0;
                *reinterpret_cast<__half2*>((__half*)C + (size_t)(row + 8) * Ntot + col) = h1;
            }
        }
    }
}

// ---------------------------------------------------------------------------
// Prep kernels
// ---------------------------------------------------------------------------
__global__ void f2h_kernel(const float4* __restrict__ in,
                           uint2* __restrict__ out, int n4) {
    int i = blockIdx.x * blockDim.x + threadIdx.x;
    if (i < n4) {
        float4 v = in[i];
        __half2 h0 = __floats2half2_rn(v.x, v.y);
        __half2 h1 = __floats2half2_rn(v.z, v.w);
        uint2 u;
        u.x = *reinterpret_cast<uint32_t*>(&h0);
        u.y = *reinterpret_cast<uint32_t*>(&h1);
        out[i] = u;
    }
}

// Stage 1: gather rpb once -> bias12[h][e]  (tiny: 12 x 2404)
__global__ void bias12_prep_kernel(const float* __restrict__ rpb,
                                   const int* __restrict__ rel_idx,
                                   float* __restrict__ out) {
    int i = blockIdx.x * blockDim.x + threadIdx.x;
    if (i < NHEADS * BM_STR) {
        const int h = i / BM_STR;
        const int e = i - h * BM_STR;
        out[i] = (e < NTOK * NTOK) ? rpb[rel_idx[e] * NHEADS + h] : 0.0f;
    }
}

// Stage 2: pure streaming fuse -> bm[(m*12+h)][e] = bias12[h][e] + mask[m][e]
__global__ void bm_stream_kernel(const float* __restrict__ bias12,
                                 const float* __restrict__ mask,
                                 float* __restrict__ out) {
    const int row = blockIdx.x;              // 0 .. NMASK*NHEADS-1 (m-major)
    const int m = row / NHEADS;
    const int h = row - m * NHEADS;
    const float* mrow = mask + (size_t)m * (NTOK * NTOK);
    const float4* brow = reinterpret_cast<const float4*>(bias12 + h * BM_STR);
    float4* orow = reinterpret_cast<float4*>(out + (size_t)row * BM_STR);
    for (int g = threadIdx.x; g < BM_STR / 4; g += 256) {
        const int e0 = g * 4;
        float4 b = brow[g];
        float4 v;
        v.x = (e0 + 0 < NTOK * NTOK) ? b.x + mrow[e0 + 0] : 0.0f;
        v.y = (e0 + 1 < NTOK * NTOK) ? b.y + mrow[e0 + 1] : 0.0f;
        v.z = (e0 + 2 < NTOK * NTOK) ? b.z + mrow[e0 + 2] : 0.0f;
        v.w = (e0 + 3 < NTOK * NTOK) ? b.w + mrow[e0 + 3] : 0.0f;
        orow[g] = v;
    }
}

// ---------------------------------------------------------------------------
// Window attention (EXACT round-8 version: 6 CTAs/SM, 49-thread softmax with
// concurrent pad-zeroing, fused bm row prefetch, P aliases dead Q/K).
// ---------------------------------------------------------------------------
__global__ __launch_bounds__(128, 6)
void win_attn_kernel(const __half* __restrict__ qkv,
                     const float* __restrict__ bm,
                     __half* __restrict__ attout) {
    const int w = blockIdx.x / NHEADS;
    const int h = blockIdx.x % NHEADS;
    const int tid  = threadIdx.x;
    const int warp = tid >> 5;
    const int lane = tid & 31;
    const int gid  = lane >> 2;
    const int tig  = lane & 3;

    __shared__ __align__(16) char  ub[64 * 40 * 2 * 2];
    __shared__ __align__(16) __half Vh[64][40];
    __shared__ __align__(16) float  Sf[NTOK][57];
    __shared__ __align__(16) float  BMs[BM_STR];

    __half (*Qh)[40] = reinterpret_cast<__half(*)[40]>(ub);
    __half (*Kh)[40] = reinterpret_cast<__half(*)[40]>(ub + 64 * 40 * 2);
    __half (*Ph)[72] = reinterpret_cast<__half(*)[72]>(ub);

    // ---- Prefetch: qkv rows (588 x 16B) + bm row (601 x 16B) ----
    const __half* base = qkv + (size_t)w * NTOK * QKV_N + h * HD;
    for (int idx = tid; idx < 3 * NTOK * 4; idx += 128) {
        const int m = idx / (NTOK * 4);
        const int rem = idx - m * (NTOK * 4);
        const int i = rem >> 2;
        const int g = rem & 3;
        __half* dst = (m == 0) ? &Qh[i][0] : (m == 1) ? &Kh[i][0] : &Vh[i][0];
        cpa16(smem_u32(dst + g * 8), base + (size_t)i * QKV_N + m * DIM + g * 8);
    }
    {
        const float* bmrow = bm + (size_t)((w & (NMASK - 1)) * NHEADS + h) * BM_STR;
        for (int idx = tid; idx < BM_STR / 4; idx += 128)
            cpa16(smem_u32(&BMs[idx * 4]), bmrow + idx * 4);
    }
    CP_COMMIT();

    // ---- Zero pad rows 49..63 of Q/K/V while loads are in flight ----
    const uint4 z4 = make_uint4(0, 0, 0, 0);
    for (int idx = tid; idx < 225; idx += 128) {
        const int a = idx / 75;
        const int rem = idx - a * 75;
        const int r = 49 + rem / 5;
        const int g = rem % 5;
        __half* dst = (a == 0) ? &Qh[r][0] : (a == 1) ? &Kh[r][0] : &Vh[r][0];
        reinterpret_cast<uint4*>(dst)[g] = z4;
    }
    CP_WAIT0();
    __syncthreads();

    // ---- Scores: S = Q K^T ----
    const uint32_t QS = smem_u32(&Qh[0][0]);
    const uint32_t KS = smem_u32(&Kh[0][0]);
    const int aL = ((lane & 7) + 8 * ((lane >> 3) & 1)) * 20 + 4 * (lane >> 4);
    const int bL = ((lane & 7) + 8 * (lane >> 4)) * 20 + 4 * ((lane >> 3) & 1);

    float acc[8][4];
    #pragma unroll
    for (int a = 0; a < 8; a++)
        #pragma unroll
        for (int r = 0; r < 4; r++) acc[a][r] = 0.0f;

    #pragma unroll
    for (int ks = 0; ks < 2; ks++) {
        uint32_t af[4];
        ldsm_x4(af, QS + (uint32_t)(warp * 16 * 20 + ks * 8 + aL) * 4);
        #pragma unroll
        for (int nb = 0; nb < 4; nb++) {
            uint32_t q[4];
            ldsm_x4(q, KS + (uint32_t)(nb * 16 * 20 + ks * 8 + bL) * 4);
            mma_f16(acc[nb * 2 + 0], af, q + 0);
            mma_f16(acc[nb * 2 + 1], af, q + 2);
        }
    }

    // scores + scale + fused bias/mask from smem
    {
        const int i0 = warp * 16 + gid;
        #pragma unroll
        for (int nt = 0; nt < 8; nt++) {
            const int j = nt * 8 + 2 * tig;
            if (j < NTOK) {
                #pragma unroll
                for (int rr = 0; rr < 2; rr++) {
                    const int i = i0 + rr * 8;
                    if (i < NTOK) {
                        const int e = i * NTOK + j;
                        Sf[i][j] = fmaf(acc[nt][rr * 2], ATTN_SCALE, BMs[e]);
                        if (j + 1 < NTOK)
                            Sf[i][j + 1] = fmaf(acc[nt][rr * 2 + 1], ATTN_SCALE, BMs[e + 1]);
                    }
                }
            }
        }
    }
    __syncthreads();   // Sf complete; Q/K dead -> Ph region reusable

    // ---- Softmax rows (threads 0..48) || P pad-zeroing (threads 49..127) ----
    if (tid < NTOK) {
        const int i = tid;
        float m = -1e30f;
        #pragma unroll 7
        for (int j = 0; j < NTOK; j++) m = fmaxf(m, Sf[i][j]);
        float s = 0.0f;
        #pragma unroll 7
        for (int j = 0; j < NTOK; j++) {
            const float e = __expf(Sf[i][j] - m);
            Sf[i][j] = e;
            s += e;
        }
        const float inv = 1.0f / s;
        #pragma unroll 7
        for (int j = 0; j < NTOK; j++)
            Ph[i][j] = __float2half_rn(Sf[i][j] * inv);
        #pragma unroll
        for (int j = NTOK; j < 56; j++)
            Ph[i][j] = __ushort_as_half((unsigned short)0);
    } else {
        for (int idx = tid - NTOK; idx < 233; idx += 128 - NTOK) {
            int r, c;
            if (idx < 135) { r = 49 + idx / 9; c = (idx % 9) * 8; }
            else           { const int q = idx - 135; r = q >> 1; c = 56 + (q & 1) * 8; }
            *reinterpret_cast<uint4*>(&Ph[r][c]) = z4;
        }
    }
    __syncthreads();

    // ---- PV: O = P V ----
    const uint32_t PS = smem_u32(&Ph[0][0]);
    const uint32_t VS = smem_u32(&Vh[0][0]);
    const int aLp = ((lane & 7) + 8 * ((lane >> 3) & 1)) * 36 + 4 * (lane >> 4);
    const int vL  = ((lane & 7) + 8 * ((lane >> 3) & 1)) * 20 + 4 * (lane >> 4);

    float pacc[4][4];
    #pragma unroll
    for (int a = 0; a < 4; a++)
        #pragma unroll
        for (int r = 0; r < 4; r++) pacc[a][r] = 0.0f;

    #pragma unroll
    for (int ks = 0; ks < 4; ks++) {
        uint32_t pf[4];
        ldsm_x4(pf, PS + (uint32_t)(warp * 16 * 36 + ks * 8 + aLp) * 4);
        uint32_t v0[4], v1[4];
        ldsm_x4_t(v0, VS + (uint32_t)(ks * 16 * 20 + vL) * 4);
        ldsm_x4_t(v1, VS + (uint32_t)(ks * 16 * 20 + 8 + vL) * 4);
        mma_f16(pacc[0], pf, v0 + 0);
        mma_f16(pacc[1], pf, v0 + 2);
        mma_f16(pacc[2], pf, v1 + 0);
        mma_f16(pacc[3], pf, v1 + 2);
    }

    // ---- Store O (fp16) ----
    {
        __half* ob = attout + (size_t)w * NTOK * DIM + h * HD;
        const int i0 = warp * 16 + gid;
        #pragma unroll
        for (int nt = 0; nt < 4; nt++) {
            const int d = nt * 8 + 2 * tig;
            #pragma unroll
            for (int rr = 0; rr < 2; rr++) {
                const int i = i0 + rr * 8;
                if (i < NTOK) {
                    __half2 hv = __floats2half2_rn(pacc[nt][rr * 2], pacc[nt][rr * 2 + 1]);
                    *reinterpret_cast<__half2*>(ob + (size_t)i * DIM + d) = hv;
                }
            }
        }
    }
}

// ---------------------------------------------------------------------------
// Launch
// ---------------------------------------------------------------------------
extern "C" void kernel_launch(void* const* d_in, const int* in_sizes, int n_in,
                              void* d_out, int out_size) {
    const float* x      = (const float*)d_in[0];
    const float* mask   = (const float*)d_in[1];
    const float* rpb    = (const float*)d_in[2];
    const float* qkv_w  = (const float*)d_in[3];
    const float* qkv_b  = (const float*)d_in[4];
    const float* proj_w = (const float*)d_in[5];
    const float* proj_b = (const float*)d_in[6];
    const int*   rel_i  = (const int*)d_in[7];
    float* out = (float*)d_out;

    __half *qkvh, *xh, *ah, *wqh, *wph;
    float *bmb, *biasb;
    cudaGetSymbolAddress((void**)&qkvh, g_qkvh);
    cudaGetSymbolAddress((void**)&xh,  g_xh);
    cudaGetSymbolAddress((void**)&ah,  g_ah);
    cudaGetSymbolAddress((void**)&wqh, g_wqh);
    cudaGetSymbolAddress((void**)&wph, g_wph);
    cudaGetSymbolAddress((void**)&bmb, g_bm);
    cudaGetSymbolAddress((void**)&biasb, g_bias12);

    cudaFuncSetAttribute(gemm_mma_kernel<__half>,
                         cudaFuncAttributeMaxDynamicSharedMemorySize, SMEM_TOT);
    cudaFuncSetAttribute(gemm_mma_kernel<float>,
                         cudaFuncAttributeMaxDynamicSharedMemorySize, SMEM_TOT);

    // conversions + two-stage bias/mask precompute
    {
        int n4 = (M_TOTAL * DIM) / 4;
        f2h_kernel<<<(n4 + 255) / 256, 256>>>((const float4*)x, (uint2*)xh, n4);
        int w4 = (QKV_N * DIM) / 4;
        f2h_kernel<<<(w4 + 255) / 256, 256>>>((const float4*)qkv_w, (uint2*)wqh, w4);
        int p4 = (DIM * DIM) / 4;
        f2h_kernel<<<(p4 + 255) / 256, 256>>>((const float4*)proj_w, (uint2*)wph, p4);
        bias12_prep_kernel<<<(NHEADS * BM_STR + 255) / 256, 256>>>(rpb, rel_i, biasb);
        bm_stream_kernel<<<NMASK * NHEADS, 256>>>(biasb, mask, bmb);
    }

    // 1) QKV projection -> fp16 qkv
    {
        dim3 grid(QKV_N / 128, M_TOTAL / 128);
        gemm_mma_kernel<__half><<<grid, 256, SMEM_TOT>>>(xh, wqh, qkv_b, qkvh, QKV_N);
    }

    // 2) Windowed attention (exact round-8 kernel)
    win_attn_kernel<<<NWIN * NHEADS, 128>>>(qkvh, bmb, ah);

    // 3) Output projection -> fp32 d_out
    {
        dim3 grid(DIM / 128, M_TOTAL / 128);
        gemm_mma_kernel<float><<<grid, 256, SMEM_TOT>>>(ah, wph, proj_b, out, DIM);
    }
}